// round 8
// baseline (speedup 1.0000x reference)
#include <cuda_runtime.h>
#include <cuda_bf16.h>
#include <cstdint>

// BasicMFNet: embed_user [8192,64] f32, embed_item [16384,64] f32,
// indices [2,200000] (int32 or int64 — detected at runtime), ratings [200000] f32.
// Output: pred [U*I] | label [U*I] | ratio (1)  -- all float32.
constexpr int U = 8192;
constexpr int I = 16384;
constexpr int H = 64;

constexpr int TILE = 128;        // M and N tile
constexpr int NCOLF = I / TILE;  // 128 column-tile flags
constexpr int NROWF = U / TILE;  // 64 row-tile flags

__device__ int g_umask[U];
__device__ int g_imask[I];
__device__ int g_colflag[NCOLF];
__device__ int g_rowflag[NROWF];
__device__ int g_idx_is_i32;     // 1 if indices buffer is int32, 0 if int64

// ---------------------------------------------------------------------------
// Packed f32x2 helpers (Blackwell FFMA2 — PTX-only path, 2x fp32 FMA rate)
// ---------------------------------------------------------------------------
__device__ __forceinline__ unsigned long long dup_f32(float x) {
    unsigned long long r;
    unsigned xi = __float_as_uint(x);
    asm("mov.b64 %0, {%1, %1};" : "=l"(r) : "r"(xi));
    return r;
}
__device__ __forceinline__ void ffma2(unsigned long long& d,
                                      unsigned long long a,
                                      unsigned long long b) {
    asm("fma.rn.f32x2 %0, %1, %2, %0;" : "+l"(d) : "l"(a), "l"(b));
}

__device__ __forceinline__ void read_uv(const void* idx, int nnz, int t,
                                        int& u, int& v) {
    if (g_idx_is_i32) {
        const int* p = (const int*)idx;
        u = p[t];
        v = p[nnz + t];
    } else {
        const long long* p = (const long long*)idx;
        u = (int)p[t];
        v = (int)p[nnz + t];
    }
}

// ---------------------------------------------------------------------------
// Kernel 1: init — zero masks/flags; block 0 detects index dtype and writes
// the ratio output. (int64 values < 2^31 have every odd int32 word == 0.)
// ---------------------------------------------------------------------------
__global__ void k_init(const int* __restrict__ idx_w32, int n_words,
                       float* __restrict__ out, int nnz, long long out_size) {
    int t = blockIdx.x * blockDim.x + threadIdx.x;
    if (t < U) g_umask[t] = 0;
    if (t < I) g_imask[t] = 0;
    if (t < NCOLF) g_colflag[t] = 0;
    if (t < NROWF) g_rowflag[t] = 0;
    if (blockIdx.x == 0) {
        __shared__ int s_found;
        if (threadIdx.x == 0) s_found = 0;
        __syncthreads();
        int found = 0;
        for (int w = 2 * (int)threadIdx.x + 1; w < n_words; w += 2 * (int)blockDim.x)
            if (idx_w32[w] != 0) found = 1;
        if (found) s_found = 1;
        __syncthreads();
        if (threadIdx.x == 0) {
            g_idx_is_i32 = s_found;
            if (out_size > 2ll * U * I)
                out[2ull * U * I] = (float)(((double)U * (double)I) / (double)nnz);
        }
    }
}

// ---------------------------------------------------------------------------
// Kernel 2: set masks + tile flags from indices (bounds-guarded)
// ---------------------------------------------------------------------------
__global__ void k_set_masks(const void* __restrict__ idx, int nnz) {
    int t = blockIdx.x * blockDim.x + threadIdx.x;
    if (t >= nnz) return;
    int u, v;
    read_uv(idx, nnz, t, u, v);
    if (u >= 0 && u < U) { g_umask[u] = 1; g_rowflag[u >> 7] = 1; }
    if (v >= 0 && v < I) { g_imask[v] = 1; g_colflag[v >> 7] = 1; }
}

// ---------------------------------------------------------------------------
// Kernel 3: GEMM  pred = (masked eu) * (masked ei)^T.
// 128x128 tile, 512 threads, 4x8 microtile (rows tm4..tm4+3, cols tn4 & tn4+64)
// -> acc is only 32 regs, so launch_bounds(512,2) gives 32 warps/SM (2 CTAs)
// vs 16 before: double the latency-hiding warps at identical FLOP count.
// Masking is applied during the smem load phase (mask reads are L1 hits),
// eliminating the separate masked-copy kernel and its 6 MB round trip.
// Conflict-free LDS: B cols split 4+4 at stride 64 (lanes 0-15 cover 256
// consecutive bytes), A is a 2-address broadcast. Epilogue zero-fills the
// matching label tile (overlaps the 537 MB label zeroing with compute).
// ---------------------------------------------------------------------------
__global__ void __launch_bounds__(512, 2) k_gemm(const float* __restrict__ eu,
                                                 const float* __restrict__ ei,
                                                 float* __restrict__ out) {
    const int bx = blockIdx.x;            // column tile (items)
    const int by = blockIdx.y;            // row tile (users)
    const int m0 = by * TILE;
    const int n0 = bx * TILE;
    const int tid = threadIdx.x;
    const int tm4 = (tid >> 4) * 4;       // 32 row-groups of 4
    const int tn4 = (tid & 15) * 4;       // 16 col-groups; cols tn4 and tn4+64

    float* pred  = out;
    float* label = out + (size_t)U * I;

    const bool active = (g_rowflag[by] != 0) && (g_colflag[bx] != 0);

    if (!active) {
        const ulonglong2 z = make_ulonglong2(0ull, 0ull);
        #pragma unroll
        for (int i = 0; i < 4; i++) {
            size_t off = (size_t)(m0 + tm4 + i) * I + n0 + tn4;
            *reinterpret_cast<ulonglong2*>(pred + off)       = z;
            *reinterpret_cast<ulonglong2*>(pred + off + 64)  = z;
            *reinterpret_cast<ulonglong2*>(label + off)      = z;
            *reinterpret_cast<ulonglong2*>(label + off + 64) = z;
        }
        return;
    }

    __shared__ float As[H][TILE];   // k-major (transposed) tiles, 32 KB each
    __shared__ float Bs[H][TILE];

    // Load+mask+transpose: 128 rows x 64 k per tile; lanes stride rows ->
    // conflict-free STS.32 (bank = r). 8 LDG.128 + 8 mask LDG per thread.
    #pragma unroll
    for (int it = 0; it < 4; it++) {
        int id = tid + it * 512;          // 0..2047
        int r = id & 127;
        int c = id >> 7;                  // 0..15 (k-group of 4)
        float4 va = *reinterpret_cast<const float4*>(
            &eu[(size_t)(m0 + r) * H + c * 4]);
        if (!g_umask[m0 + r]) va = make_float4(0.f, 0.f, 0.f, 0.f);
        As[c * 4 + 0][r] = va.x;
        As[c * 4 + 1][r] = va.y;
        As[c * 4 + 2][r] = va.z;
        As[c * 4 + 3][r] = va.w;
        float4 vb = *reinterpret_cast<const float4*>(
            &ei[(size_t)(n0 + r) * H + c * 4]);
        if (!g_imask[n0 + r]) vb = make_float4(0.f, 0.f, 0.f, 0.f);
        Bs[c * 4 + 0][r] = vb.x;
        Bs[c * 4 + 1][r] = vb.y;
        Bs[c * 4 + 2][r] = vb.z;
        Bs[c * 4 + 3][r] = vb.w;
    }

    unsigned long long acc[4][4];    // [row][col-pair] = 32 regs
    #pragma unroll
    for (int i = 0; i < 4; i++)
        #pragma unroll
        for (int j = 0; j < 4; j++) acc[i][j] = 0ull;

    __syncthreads();

    #pragma unroll 4
    for (int k = 0; k < H; k++) {
        // A: 16B broadcast load (2 distinct addrs/warp -> ~free)
        float4 a0 = *reinterpret_cast<const float4*>(&As[k][tm4]);
        // B: lanes 0-15 read 16 consecutive 16B chunks -> conflict-free;
        // lanes 16-31 broadcast the same addresses.
        ulonglong2 b0 = *reinterpret_cast<const ulonglong2*>(&Bs[k][tn4]);
        ulonglong2 b1 = *reinterpret_cast<const ulonglong2*>(&Bs[k][tn4 + 64]);
        float av[4] = {a0.x, a0.y, a0.z, a0.w};
        #pragma unroll
        for (int i = 0; i < 4; i++) {
            unsigned long long ad = dup_f32(av[i]);
            ffma2(acc[i][0], ad, b0.x);
            ffma2(acc[i][1], ad, b0.y);
            ffma2(acc[i][2], ad, b1.x);
            ffma2(acc[i][3], ad, b1.y);
        }
    }

    // Epilogue: store pred tile + zero label tile (coalesced STG.128).
    const ulonglong2 z = make_ulonglong2(0ull, 0ull);
    #pragma unroll
    for (int i = 0; i < 4; i++) {
        size_t off = (size_t)(m0 + tm4 + i) * I + n0 + tn4;
        *reinterpret_cast<ulonglong2*>(pred + off) =
            make_ulonglong2(acc[i][0], acc[i][1]);
        *reinterpret_cast<ulonglong2*>(pred + off + 64) =
            make_ulonglong2(acc[i][2], acc[i][3]);
        *reinterpret_cast<ulonglong2*>(label + off)      = z;
        *reinterpret_cast<ulonglong2*>(label + off + 64) = z;
    }
}

// ---------------------------------------------------------------------------
// Kernel 4: scatter-add ratings into label (bounds-guarded)
// ---------------------------------------------------------------------------
__global__ void k_scatter(const void* __restrict__ idx,
                          const float* __restrict__ ratings,
                          float* __restrict__ out, int nnz) {
    int t = blockIdx.x * blockDim.x + threadIdx.x;
    if (t >= nnz) return;
    int u, v;
    read_uv(idx, nnz, t, u, v);
    if (u < 0 || u >= U || v < 0 || v >= I) return;
    float* label = out + (size_t)U * I;
    atomicAdd(&label[(size_t)u * I + v], ratings[t]);
}

// ---------------------------------------------------------------------------
extern "C" void kernel_launch(void* const* d_in, const int* in_sizes, int n_in,
                              void* d_out, int out_size) {
    const float* eu = (const float*)d_in[0];
    const float* ei = (const float*)d_in[1];
    const void*  idx = d_in[2];
    const float* ratings = (const float*)d_in[3];
    float* out = (float*)d_out;
    const int nnz = in_sizes[3];            // ratings count
    const int n_words = in_sizes[2] < 4096 ? in_sizes[2] : 4096;

    // 1. zero masks/flags + detect index dtype + ratio
    k_init<<<(I + 255) / 256, 256>>>((const int*)idx, n_words, out, nnz,
                                     (long long)out_size);
    // 2. set masks/flags from indices
    k_set_masks<<<(nnz + 255) / 256, 256>>>(idx, nnz);
    // 3. GEMM (masks applied in-load; writes pred + zeros label)
    {
        dim3 grid(I / TILE, U / TILE);
        k_gemm<<<grid, 512>>>(eu, ei, out);
    }
    // 4. scatter ratings into label
    k_scatter<<<(nnz + 255) / 256, 256>>>(idx, ratings, out, nnz);
}

// round 9
// speedup vs baseline: 1.5224x; 1.5224x over previous
#include <cuda_runtime.h>
#include <cuda_bf16.h>
#include <cstdint>

// BasicMFNet: embed_user [8192,64] f32, embed_item [16384,64] f32,
// indices [2,200000] (int32 or int64 — detected at runtime), ratings [200000] f32.
// Output: pred [U*I] | label [U*I] | ratio (1)  -- all float32.
constexpr int U = 8192;
constexpr int I = 16384;
constexpr int H = 64;

constexpr int TILE = 128;        // M and N tile
constexpr int NCOLF = I / TILE;  // 128 column-tile flags
constexpr int NROWF = U / TILE;  // 64 row-tile flags

// Device scratch (no allocations allowed anywhere).
__device__ float g_eu[U * H];     // masked user embeddings
__device__ float g_ei[I * H];     // masked item embeddings
__device__ int   g_umask[U];
__device__ int   g_imask[I];
__device__ int   g_colflag[NCOLF];
__device__ int   g_rowflag[NROWF];
__device__ int   g_idx_is_i32;    // 1 if indices buffer is int32, 0 if int64

// ---------------------------------------------------------------------------
// Packed f32x2 helpers (Blackwell FFMA2 — PTX-only path, 2x fp32 FMA rate)
// ---------------------------------------------------------------------------
__device__ __forceinline__ unsigned long long dup_f32(float x) {
    unsigned long long r;
    unsigned xi = __float_as_uint(x);
    asm("mov.b64 %0, {%1, %1};" : "=l"(r) : "r"(xi));
    return r;
}
__device__ __forceinline__ void ffma2(unsigned long long& d,
                                      unsigned long long a,
                                      unsigned long long b) {
    asm("fma.rn.f32x2 %0, %1, %2, %0;" : "+l"(d) : "l"(a), "l"(b));
}

__device__ __forceinline__ void read_uv(const void* idx, int nnz, int t,
                                        int& u, int& v) {
    if (g_idx_is_i32) {
        const int* p = (const int*)idx;
        u = p[t];
        v = p[nnz + t];
    } else {
        const long long* p = (const long long*)idx;
        u = (int)p[t];
        v = (int)p[nnz + t];
    }
}

// ---------------------------------------------------------------------------
// Kernel 1: init — zero masks/flags; block 0 detects index dtype.
// (int64 values < 2^31 have every odd int32 word == 0.)
// ---------------------------------------------------------------------------
__global__ void k_init(const int* __restrict__ idx_w32, int n_words) {
    int t = blockIdx.x * blockDim.x + threadIdx.x;
    if (t < U) g_umask[t] = 0;
    if (t < I) g_imask[t] = 0;
    if (t < NCOLF) g_colflag[t] = 0;
    if (t < NROWF) g_rowflag[t] = 0;
    if (blockIdx.x == 0) {
        __shared__ int s_found;
        if (threadIdx.x == 0) s_found = 0;
        __syncthreads();
        int found = 0;
        for (int w = 2 * (int)threadIdx.x + 1; w < n_words; w += 2 * (int)blockDim.x)
            if (idx_w32[w] != 0) found = 1;
        if (found) s_found = 1;
        __syncthreads();
        if (threadIdx.x == 0) g_idx_is_i32 = s_found;
    }
}

// ---------------------------------------------------------------------------
// Kernel 2: set masks + tile flags from indices (bounds-guarded)
// ---------------------------------------------------------------------------
__global__ void k_set_masks(const void* __restrict__ idx, int nnz) {
    int t = blockIdx.x * blockDim.x + threadIdx.x;
    if (t >= nnz) return;
    int u, v;
    read_uv(idx, nnz, t, u, v);
    if (u >= 0 && u < U) { g_umask[u] = 1; g_rowflag[u >> 7] = 1; }
    if (v >= 0 && v < I) { g_imask[v] = 1; g_colflag[v >> 7] = 1; }
}

// ---------------------------------------------------------------------------
// Kernel 3: build masked embedding copies + write ratio
// ---------------------------------------------------------------------------
__global__ void k_build_scratch(const float* __restrict__ eu,
                                const float* __restrict__ ei,
                                float* __restrict__ out, int nnz,
                                long long out_size) {
    int t = blockIdx.x * blockDim.x + threadIdx.x;
    const int NU4 = U * (H / 4);
    const int NI4 = I * (H / 4);
    if (t < NU4) {
        int row = t / (H / 4);
        float4 v = reinterpret_cast<const float4*>(eu)[t];
        if (!g_umask[row]) v = make_float4(0.f, 0.f, 0.f, 0.f);
        reinterpret_cast<float4*>(g_eu)[t] = v;
    } else if (t < NU4 + NI4) {
        int t2 = t - NU4;
        int row = t2 / (H / 4);
        float4 v = reinterpret_cast<const float4*>(ei)[t2];
        if (!g_imask[row]) v = make_float4(0.f, 0.f, 0.f, 0.f);
        reinterpret_cast<float4*>(g_ei)[t2] = v;
    }
    if (t == 0 && out_size > 2ll * U * I) {
        out[2ull * U * I] = (float)(((double)U * (double)I) / (double)nnz);
    }
}

// ---------------------------------------------------------------------------
// Kernel 4: GEMM  pred = g_eu * g_ei^T.
// 128x128 tile, 256 threads, 8x8 microtile split (4+4)x(4+4) at stride 64 ->
// conflict-free LDS.128 on both operands. Whole H=64 k-depth in smem, single
// sync. NEW vs R7: explicit k+1 register prefetch (double-buffered fragments)
// so the 29-cyc LDS latency is hidden behind the previous k's 32-FFMA2 block.
// Epilogue zero-fills the matching label tile.
// ---------------------------------------------------------------------------
__global__ void __launch_bounds__(256, 2) k_gemm(float* __restrict__ out) {
    const int bx = blockIdx.x;            // column tile (items)
    const int by = blockIdx.y;            // row tile (users)
    const int m0 = by * TILE;
    const int n0 = bx * TILE;
    const int tid = threadIdx.x;
    const int tm4a = (tid >> 4) * 4;      // 16 row-groups of 4
    const int tn4a = (tid & 15) * 4;      // 16 col-groups of 4 (consecutive 16B)

    float* pred  = out;
    float* label = out + (size_t)U * I;

    const bool active = (g_rowflag[by] != 0) && (g_colflag[bx] != 0);

    if (!active) {
        const ulonglong2 z = make_ulonglong2(0ull, 0ull);
        #pragma unroll
        for (int i = 0; i < 8; i++) {
            int row = m0 + (i < 4 ? tm4a + i : 64 + tm4a + (i - 4));
            size_t off = (size_t)row * I + n0 + tn4a;
            *reinterpret_cast<ulonglong2*>(pred + off)       = z;
            *reinterpret_cast<ulonglong2*>(pred + off + 64)  = z;
            *reinterpret_cast<ulonglong2*>(label + off)      = z;
            *reinterpret_cast<ulonglong2*>(label + off + 64) = z;
        }
        return;
    }

    __shared__ float As[H][TILE];   // k-major (transposed) tiles, 32 KB each
    __shared__ float Bs[H][TILE];

    // Single load phase: 128 rows x 64 k per tile; lanes stride rows ->
    // conflict-free STS.32 (bank = r). 16 LDG.128 per thread, high MLP.
    #pragma unroll
    for (int it = 0; it < 8; it++) {
        int id = tid + it * 256;          // 0..2047
        int r = id & 127;
        int c = id >> 7;                  // 0..15 (k-group of 4)
        float4 va = *reinterpret_cast<const float4*>(
            &g_eu[(size_t)(m0 + r) * H + c * 4]);
        As[c * 4 + 0][r] = va.x;
        As[c * 4 + 1][r] = va.y;
        As[c * 4 + 2][r] = va.z;
        As[c * 4 + 3][r] = va.w;
        float4 vb = *reinterpret_cast<const float4*>(
            &g_ei[(size_t)(n0 + r) * H + c * 4]);
        Bs[c * 4 + 0][r] = vb.x;
        Bs[c * 4 + 1][r] = vb.y;
        Bs[c * 4 + 2][r] = vb.z;
        Bs[c * 4 + 3][r] = vb.w;
    }

    unsigned long long acc[8][4];    // [row][col-pair]
    #pragma unroll
    for (int i = 0; i < 8; i++)
        #pragma unroll
        for (int j = 0; j < 4; j++) acc[i][j] = 0ull;

    __syncthreads();

    // Prime the register double buffer with k=0 fragments.
    float4 a0c = *reinterpret_cast<const float4*>(&As[0][tm4a]);
    float4 a1c = *reinterpret_cast<const float4*>(&As[0][tm4a + 64]);
    ulonglong2 b0c = *reinterpret_cast<const ulonglong2*>(&Bs[0][tn4a]);
    ulonglong2 b1c = *reinterpret_cast<const ulonglong2*>(&Bs[0][tn4a + 64]);

    #pragma unroll 8
    for (int k = 0; k < H; k++) {
        // Prefetch k+1 fragments (wrap masked to stay in-bounds; the k=63
        // prefetch is dead). These LDS issue before the FFMA2 block below,
        // so their latency hides behind ~96 cycles of compute.
        const int kn = (k + 1) & (H - 1);
        float4 a0n = *reinterpret_cast<const float4*>(&As[kn][tm4a]);
        float4 a1n = *reinterpret_cast<const float4*>(&As[kn][tm4a + 64]);
        ulonglong2 b0n = *reinterpret_cast<const ulonglong2*>(&Bs[kn][tn4a]);
        ulonglong2 b1n = *reinterpret_cast<const ulonglong2*>(&Bs[kn][tn4a + 64]);

        float av[8] = {a0c.x, a0c.y, a0c.z, a0c.w, a1c.x, a1c.y, a1c.z, a1c.w};
        #pragma unroll
        for (int i = 0; i < 8; i++) {
            unsigned long long ad = dup_f32(av[i]);
            ffma2(acc[i][0], ad, b0c.x);
            ffma2(acc[i][1], ad, b0c.y);
            ffma2(acc[i][2], ad, b1c.x);
            ffma2(acc[i][3], ad, b1c.y);
        }

        a0c = a0n; a1c = a1n; b0c = b0n; b1c = b1n;
    }

    // Epilogue: store pred tile + zero label tile. Lanes 0-15 of a warp cover
    // 256 consecutive bytes per row-chunk -> fully coalesced STG.128.
    const ulonglong2 z = make_ulonglong2(0ull, 0ull);
    #pragma unroll
    for (int i = 0; i < 8; i++) {
        int row = m0 + (i < 4 ? tm4a + i : 64 + tm4a + (i - 4));
        size_t off = (size_t)row * I + n0 + tn4a;
        *reinterpret_cast<ulonglong2*>(pred + off) =
            make_ulonglong2(acc[i][0], acc[i][1]);
        *reinterpret_cast<ulonglong2*>(pred + off + 64) =
            make_ulonglong2(acc[i][2], acc[i][3]);
        *reinterpret_cast<ulonglong2*>(label + off)      = z;
        *reinterpret_cast<ulonglong2*>(label + off + 64) = z;
    }
}

// ---------------------------------------------------------------------------
// Kernel 5: scatter-add ratings into label (bounds-guarded)
// ---------------------------------------------------------------------------
__global__ void k_scatter(const void* __restrict__ idx,
                          const float* __restrict__ ratings,
                          float* __restrict__ out, int nnz) {
    int t = blockIdx.x * blockDim.x + threadIdx.x;
    if (t >= nnz) return;
    int u, v;
    read_uv(idx, nnz, t, u, v);
    if (u < 0 || u >= U || v < 0 || v >= I) return;
    float* label = out + (size_t)U * I;
    atomicAdd(&label[(size_t)u * I + v], ratings[t]);
}

// ---------------------------------------------------------------------------
extern "C" void kernel_launch(void* const* d_in, const int* in_sizes, int n_in,
                              void* d_out, int out_size) {
    const float* eu = (const float*)d_in[0];
    const float* ei = (const float*)d_in[1];
    const void*  idx = d_in[2];
    const float* ratings = (const float*)d_in[3];
    float* out = (float*)d_out;
    const int nnz = in_sizes[3];            // ratings count
    const int n_words = in_sizes[2] < 4096 ? in_sizes[2] : 4096;

    // 1. zero masks/flags + detect index dtype
    k_init<<<(I + 255) / 256, 256>>>((const int*)idx, n_words);
    // 2. set masks/flags from indices
    k_set_masks<<<(nnz + 255) / 256, 256>>>(idx, nnz);
    // 3. masked embedding copies + ratio
    {
        int total = U * (H / 4) + I * (H / 4);
        k_build_scratch<<<(total + 255) / 256, 256>>>(eu, ei, out, nnz,
                                                      (long long)out_size);
    }
    // 4. GEMM (writes pred + zeros label)
    {
        dim3 grid(I / TILE, U / TILE);
        k_gemm<<<grid, 256>>>(out);
    }
    // 5. scatter ratings into label
    k_scatter<<<(nnz + 255) / 256, 256>>>(idx, ratings, out, nnz);
}

// round 11
// speedup vs baseline: 1.6122x; 1.0590x over previous
#include <cuda_runtime.h>
#include <cuda_bf16.h>
#include <cstdint>

// BasicMFNet: embed_user [8192,64] f32, embed_item [16384,64] f32,
// indices [2,200000] (int32 or int64 — detected at runtime), ratings [200000] f32.
// Output: pred [U*I] | label [U*I] | ratio (1)  -- all float32.
constexpr int U = 8192;
constexpr int I = 16384;
constexpr int H = 64;

constexpr int TILE = 128;        // M and N tile
constexpr int NCOLF = I / TILE;  // 128 column-tile flags
constexpr int NROWF = U / TILE;  // 64 row-tile flags

// Device scratch (no allocations allowed anywhere).
__device__ float g_eu[U * H];     // masked user embeddings
__device__ float g_ei[I * H];     // masked item embeddings
__device__ int   g_umask[U];
__device__ int   g_imask[I];
__device__ int   g_colflag[NCOLF];
__device__ int   g_rowflag[NROWF];
__device__ int   g_idx_is_i32;    // 1 if indices buffer is int32, 0 if int64

// ---------------------------------------------------------------------------
// Packed f32x2 helpers (Blackwell FFMA2 — PTX-only path, 2x fp32 FMA rate)
// ---------------------------------------------------------------------------
union U64F2 { unsigned long long u; float2 f; };

__device__ __forceinline__ unsigned long long dup_f32(float x) {
    unsigned long long r;
    unsigned xi = __float_as_uint(x);
    asm("mov.b64 %0, {%1, %1};" : "=l"(r) : "r"(xi));
    return r;
}
__device__ __forceinline__ void ffma2(unsigned long long& d,
                                      unsigned long long a,
                                      unsigned long long b) {
    asm("fma.rn.f32x2 %0, %1, %2, %0;" : "+l"(d) : "l"(a), "l"(b));
}

__device__ __forceinline__ void read_uv(const void* idx, int nnz, int t,
                                        int& u, int& v) {
    if (g_idx_is_i32) {
        const int* p = (const int*)idx;
        u = p[t];
        v = p[nnz + t];
    } else {
        const long long* p = (const long long*)idx;
        u = (int)p[t];
        v = (int)p[nnz + t];
    }
}

// ---------------------------------------------------------------------------
// Kernel 1: init — zero masks/flags; block 0 detects index dtype.
// (int64 values < 2^31 have every odd int32 word == 0.)
// ---------------------------------------------------------------------------
__global__ void k_init(const int* __restrict__ idx_w32, int n_words) {
    int t = blockIdx.x * blockDim.x + threadIdx.x;
    if (t < U) g_umask[t] = 0;
    if (t < I) g_imask[t] = 0;
    if (t < NCOLF) g_colflag[t] = 0;
    if (t < NROWF) g_rowflag[t] = 0;
    if (blockIdx.x == 0) {
        __shared__ int s_found;
        if (threadIdx.x == 0) s_found = 0;
        __syncthreads();
        int found = 0;
        for (int w = 2 * (int)threadIdx.x + 1; w < n_words; w += 2 * (int)blockDim.x)
            if (idx_w32[w] != 0) found = 1;
        if (found) s_found = 1;
        __syncthreads();
        if (threadIdx.x == 0) g_idx_is_i32 = s_found;
    }
}

// ---------------------------------------------------------------------------
// Kernel 2: set masks + tile flags from indices (bounds-guarded)
// ---------------------------------------------------------------------------
__global__ void k_set_masks(const void* __restrict__ idx, int nnz) {
    int t = blockIdx.x * blockDim.x + threadIdx.x;
    if (t >= nnz) return;
    int u, v;
    read_uv(idx, nnz, t, u, v);
    if (u >= 0 && u < U) { g_umask[u] = 1; g_rowflag[u >> 7] = 1; }
    if (v >= 0 && v < I) { g_imask[v] = 1; g_colflag[v >> 7] = 1; }
}

// ---------------------------------------------------------------------------
// Kernel 3: build masked embedding copies + write ratio
// ---------------------------------------------------------------------------
__global__ void k_build_scratch(const float* __restrict__ eu,
                                const float* __restrict__ ei,
                                float* __restrict__ out, int nnz,
                                long long out_size) {
    int t = blockIdx.x * blockDim.x + threadIdx.x;
    const int NU4 = U * (H / 4);
    const int NI4 = I * (H / 4);
    if (t < NU4) {
        int row = t / (H / 4);
        float4 v = reinterpret_cast<const float4*>(eu)[t];
        if (!g_umask[row]) v = make_float4(0.f, 0.f, 0.f, 0.f);
        reinterpret_cast<float4*>(g_eu)[t] = v;
    } else if (t < NU4 + NI4) {
        int t2 = t - NU4;
        int row = t2 / (H / 4);
        float4 v = reinterpret_cast<const float4*>(ei)[t2];
        if (!g_imask[row]) v = make_float4(0.f, 0.f, 0.f, 0.f);
        reinterpret_cast<float4*>(g_ei)[t2] = v;
    }
    if (t == 0 && out_size > 2ll * U * I) {
        out[2ull * U * I] = (float)(((double)U * (double)I) / (double)nnz);
    }
}

// ---------------------------------------------------------------------------
// Kernel 4: GEMM  pred = g_eu * g_ei^T.
// 128x128 tile, 256 threads. Microtile mapping (crossbar fix vs R7):
//   warp w (0..7) owns rows 16w..16w+15, lane l owns cols 4l..4l+3.
// Per k per warp: B = ONE LDS.128 with all 32 lanes distinct (4 wavefronts),
// A = four 16B broadcast LDS.128 (~4 wavefronts) -> ~8 wf/k vs ~24 in R7's
// mapping (lanes 16-31 no longer replay lanes 0-15's addresses).
// acc packs row pairs: A pairs load directly as u64 (no dup); only the 4 B
// values need dup-MOVs. Whole H=64 in smem, single sync. Epilogue zero-fills
// the matching label tile (fused with pred stores).
// ---------------------------------------------------------------------------
__global__ void __launch_bounds__(256, 2) k_gemm(float* __restrict__ out) {
    const int bx = blockIdx.x;            // column tile (items)
    const int by = blockIdx.y;            // row tile (users)
    const int m0 = by * TILE;
    const int n0 = bx * TILE;
    const int tid = threadIdx.x;
    const int wid = tid >> 5;             // 0..7
    const int lid = tid & 31;
    const int rows0 = wid * 16;           // 16 rows per warp
    const int col0  = lid * 4;            // 4 cols per lane

    float* pred  = out;
    float* label = out + (size_t)U * I;

    const bool active = (g_rowflag[by] != 0) && (g_colflag[bx] != 0);

    if (!active) {
        const ulonglong2 z = make_ulonglong2(0ull, 0ull);
        #pragma unroll
        for (int r = 0; r < 16; r++) {
            size_t off = (size_t)(m0 + rows0 + r) * I + n0 + col0;
            *reinterpret_cast<ulonglong2*>(pred + off)  = z;
            *reinterpret_cast<ulonglong2*>(label + off) = z;
        }
        return;
    }

    __shared__ float As[H][TILE];   // k-major (transposed) tiles, 32 KB each
    __shared__ float Bs[H][TILE];

    // Single load phase: 128 rows x 64 k per tile; lanes stride rows ->
    // conflict-free STS.32 (bank = r). 16 LDG.128 per thread, high MLP.
    #pragma unroll
    for (int it = 0; it < 8; it++) {
        int id = tid + it * 256;          // 0..2047
        int r = id & 127;
        int c = id >> 7;                  // 0..15 (k-group of 4)
        float4 va = *reinterpret_cast<const float4*>(
            &g_eu[(size_t)(m0 + r) * H + c * 4]);
        As[c * 4 + 0][r] = va.x;
        As[c * 4 + 1][r] = va.y;
        As[c * 4 + 2][r] = va.z;
        As[c * 4 + 3][r] = va.w;
        float4 vb = *reinterpret_cast<const float4*>(
            &g_ei[(size_t)(n0 + r) * H + c * 4]);
        Bs[c * 4 + 0][r] = vb.x;
        Bs[c * 4 + 1][r] = vb.y;
        Bs[c * 4 + 2][r] = vb.z;
        Bs[c * 4 + 3][r] = vb.w;
    }

    // acc[i][j]: row pair (rows0+2i, rows0+2i+1), col (col0+j). 32 u64.
    U64F2 acc[8][4];
    #pragma unroll
    for (int i = 0; i < 8; i++)
        #pragma unroll
        for (int j = 0; j < 4; j++) acc[i][j].u = 0ull;

    __syncthreads();

    #pragma unroll 8
    for (int k = 0; k < H; k++) {
        // A: 16 consecutive rows as 8 u64 pairs via 4 broadcast LDS.128
        // (one address per warp each -> ~1 wavefront each).
        ulonglong2 ap0 = *reinterpret_cast<const ulonglong2*>(&As[k][rows0 + 0]);
        ulonglong2 ap1 = *reinterpret_cast<const ulonglong2*>(&As[k][rows0 + 4]);
        ulonglong2 ap2 = *reinterpret_cast<const ulonglong2*>(&As[k][rows0 + 8]);
        ulonglong2 ap3 = *reinterpret_cast<const ulonglong2*>(&As[k][rows0 + 12]);
        // B: one LDS.128, all 32 lanes distinct, 512B contiguous -> 4 wf,
        // conflict-free (each 8-lane phase spans 128B = all banks once).
        float4 bv = *reinterpret_cast<const float4*>(&Bs[k][col0]);
        unsigned long long bd0 = dup_f32(bv.x);
        unsigned long long bd1 = dup_f32(bv.y);
        unsigned long long bd2 = dup_f32(bv.z);
        unsigned long long bd3 = dup_f32(bv.w);

        unsigned long long ap[8] = {ap0.x, ap0.y, ap1.x, ap1.y,
                                    ap2.x, ap2.y, ap3.x, ap3.y};
        #pragma unroll
        for (int i = 0; i < 8; i++) {
            ffma2(acc[i][0].u, ap[i], bd0);
            ffma2(acc[i][1].u, ap[i], bd1);
            ffma2(acc[i][2].u, ap[i], bd2);
            ffma2(acc[i][3].u, ap[i], bd3);
        }
    }

    // Epilogue: store pred tile + zero label tile. Lanes of a warp cover 512
    // consecutive bytes per row -> fully coalesced STG.128.
    const ulonglong2 z = make_ulonglong2(0ull, 0ull);
    #pragma unroll
    for (int i = 0; i < 8; i++) {
        size_t off0 = (size_t)(m0 + rows0 + 2 * i) * I + n0 + col0;
        size_t off1 = off0 + I;
        float4 p0 = make_float4(acc[i][0].f.x, acc[i][1].f.x,
                                acc[i][2].f.x, acc[i][3].f.x);
        float4 p1 = make_float4(acc[i][0].f.y, acc[i][1].f.y,
                                acc[i][2].f.y, acc[i][3].f.y);
        *reinterpret_cast<float4*>(pred + off0) = p0;
        *reinterpret_cast<float4*>(pred + off1) = p1;
        *reinterpret_cast<ulonglong2*>(label + off0) = z;
        *reinterpret_cast<ulonglong2*>(label + off1) = z;
    }
}

// ---------------------------------------------------------------------------
// Kernel 5: scatter-add ratings into label (bounds-guarded)
// ---------------------------------------------------------------------------
__global__ void k_scatter(const void* __restrict__ idx,
                          const float* __restrict__ ratings,
                          float* __restrict__ out, int nnz) {
    int t = blockIdx.x * blockDim.x + threadIdx.x;
    if (t >= nnz) return;
    int u, v;
    read_uv(idx, nnz, t, u, v);
    if (u < 0 || u >= U || v < 0 || v >= I) return;
    float* label = out + (size_t)U * I;
    atomicAdd(&label[(size_t)u * I + v], ratings[t]);
}

// ---------------------------------------------------------------------------
extern "C" void kernel_launch(void* const* d_in, const int* in_sizes, int n_in,
                              void* d_out, int out_size) {
    const float* eu = (const float*)d_in[0];
    const float* ei = (const float*)d_in[1];
    const void*  idx = d_in[2];
    const float* ratings = (const float*)d_in[3];
    float* out = (float*)d_out;
    const int nnz = in_sizes[3];            // ratings count
    const int n_words = in_sizes[2] < 4096 ? in_sizes[2] : 4096;

    // 1. zero masks/flags + detect index dtype
    k_init<<<(I + 255) / 256, 256>>>((const int*)idx, n_words);
    // 2. set masks/flags from indices
    k_set_masks<<<(nnz + 255) / 256, 256>>>(idx, nnz);
    // 3. masked embedding copies + ratio
    {
        int total = U * (H / 4) + I * (H / 4);
        k_build_scratch<<<(total + 255) / 256, 256>>>(eu, ei, out, nnz,
                                                      (long long)out_size);
    }
    // 4. GEMM (writes pred + zeros label)
    {
        dim3 grid(I / TILE, U / TILE);
        k_gemm<<<grid, 256>>>(out);
    }
    // 5. scatter ratings into label
    k_scatter<<<(nnz + 255) / 256, 256>>>(idx, ratings, out, nnz);
}